// round 1
// baseline (speedup 1.0000x reference)
#include <cuda_runtime.h>
#include <math.h>

// Problem constants
#define Bb 32
#define Tt 60
#define Ii 577
#define Hh 768
#define Pp 384
#define Gg 256
#define Cc 128
#define Nn 637   // Ii + Tt

// ---------------------------------------------------------------------------
// Scratch (static __device__ globals; no allocation anywhere)
// ---------------------------------------------------------------------------
__device__ float g_feat_t[(size_t)Bb * Tt * Hh];          // 1.47M
__device__ float g_feat_v[(size_t)Bb * Ii * Hh];          // 14.2M
__device__ float g_x[(size_t)Bb * Nn * Pp];               // 7.8M
__device__ float g_h[(size_t)Bb * Nn * Gg];               // 5.2M
__device__ float g_gat[(size_t)Bb * Nn * Gg];             // 5.2M
__device__ float g_Pmat[(size_t)Bb * Nn * Nn];            // 13.0M (52MB)
__device__ float g_el[Bb * Nn];
__device__ float g_er[Bb * Nn];
__device__ float g_hgi[Bb * Pp];
__device__ float g_hgt[Bb * Pp];
__device__ float g_part[2 * Bb];

// ---------------------------------------------------------------------------
// Generic tiled SGEMM with fused bias + activation + optional row remap.
// C[M,N] = act(A[M,K] @ B[K,N] + bias), batched via blockIdx.z strides.
// rowsPer > 0 remaps output row r -> (r/rowsPer)*Nn + rowOff + r%rowsPer
// (used to scatter proj_v / proj_t into the concatenated x buffer).
// ---------------------------------------------------------------------------
#define BM 64
#define BN 64
#define BK 16

#define ACT_NONE 0
#define ACT_SIG  1
#define ACT_RELU 2
#define ACT_ELU  3

__global__ __launch_bounds__(256) void sgemm_kernel(
    const float* __restrict__ A, const float* __restrict__ Bm,
    const float* __restrict__ bias, float* __restrict__ C,
    int M, int N, int K, int ldc,
    long sA, long sB, long sC,
    int mode, int rowsPer, int rowOff)
{
    A  += (long)blockIdx.z * sA;
    Bm += (long)blockIdx.z * sB;
    C  += (long)blockIdx.z * sC;

    __shared__ float As[BK][BM];
    __shared__ float Bs[BK][BN];

    int tid = threadIdx.x;
    int tx = tid & 15;         // 0..15  -> 4 output cols each
    int ty = tid >> 4;         // 0..15  -> 4 output rows each
    int row0 = blockIdx.y * BM;
    int col0 = blockIdx.x * BN;

    float acc[4][4] = {};

    for (int k0 = 0; k0 < K; k0 += BK) {
        // A tile: BM x BK = 1024 elems, transposed into As[c][r]
        #pragma unroll
        for (int j = 0; j < 4; j++) {
            int i = tid + j * 256;
            int r = i >> 4, c = i & 15;
            int gr = row0 + r, gc = k0 + c;
            As[c][r] = (gr < M && gc < K) ? A[(long)gr * K + gc] : 0.f;
        }
        // B tile: BK x BN = 1024 elems
        #pragma unroll
        for (int j = 0; j < 4; j++) {
            int i = tid + j * 256;
            int r = i >> 6, c = i & 63;
            int gr = k0 + r, gc = col0 + c;
            Bs[r][c] = (gr < K && gc < N) ? Bm[(long)gr * N + gc] : 0.f;
        }
        __syncthreads();

        #pragma unroll
        for (int kk = 0; kk < BK; kk++) {
            float a[4], b[4];
            #pragma unroll
            for (int u = 0; u < 4; u++) a[u] = As[kk][ty * 4 + u];
            #pragma unroll
            for (int u = 0; u < 4; u++) b[u] = Bs[kk][tx * 4 + u];
            #pragma unroll
            for (int u = 0; u < 4; u++)
                #pragma unroll
                for (int v = 0; v < 4; v++)
                    acc[u][v] = fmaf(a[u], b[v], acc[u][v]);
        }
        __syncthreads();
    }

    #pragma unroll
    for (int u = 0; u < 4; u++) {
        int r = row0 + ty * 4 + u;
        if (r >= M) continue;
        long orow = r;
        if (rowsPer > 0) orow = (long)(r / rowsPer) * Nn + rowOff + (r % rowsPer);
        #pragma unroll
        for (int v = 0; v < 4; v++) {
            int c = col0 + tx * 4 + v;
            if (c >= N) continue;
            float val = acc[u][v];
            if (bias) val += bias[c];
            if (mode == ACT_SIG)       val = 1.f / (1.f + expf(-val));
            else if (mode == ACT_RELU) val = fmaxf(val, 0.f);
            else if (mode == ACT_ELU)  val = val > 0.f ? val : expm1f(val);
            C[orow * (long)ldc + c] = val;
        }
    }
}

// ---------------------------------------------------------------------------
// Per-row scores: el[row] = h[row,:] . al,  er[row] = h[row,:] . ar  (G=256)
// ---------------------------------------------------------------------------
__global__ void score_kernel(const float* __restrict__ h,
                             const float* __restrict__ al,
                             const float* __restrict__ ar,
                             float* __restrict__ el, float* __restrict__ er)
{
    int row = blockIdx.x;
    const float* hr = h + (long)row * Gg;
    int t = threadIdx.x;   // 128
    float a = hr[t] * al[t] + hr[t + 128] * al[t + 128];
    float b = hr[t] * ar[t] + hr[t + 128] * ar[t + 128];
    __shared__ float sa[128], sb[128];
    sa[t] = a; sb[t] = b; __syncthreads();
    for (int o = 64; o > 0; o >>= 1) {
        if (t < o) { sa[t] += sa[t + o]; sb[t] += sb[t + o]; }
        __syncthreads();
    }
    if (t == 0) { el[row] = sa[0]; er[row] = sb[0]; }
}

// ---------------------------------------------------------------------------
// Build normalized attention matrix:
// P[b,d,s] = (s==d) ? 0 : exp(lrelu(el[b,s]+er[b,d])) / Z(b,d)
// One block per (b,d) row. Single pass: values kept in registers.
// ---------------------------------------------------------------------------
__global__ void build_p_kernel(const float* __restrict__ el,
                               const float* __restrict__ er,
                               float* __restrict__ Pm)
{
    int row = blockIdx.x;              // b*Nn + d
    int b = row / Nn, d = row % Nn;
    const float* elb = el + b * Nn;
    float erd = er[row];
    float* pr = Pm + (long)row * Nn;
    int t = threadIdx.x;               // 256

    float vals[3];
    float s = 0.f;
    #pragma unroll
    for (int it = 0; it < 3; it++) {
        int sIdx = t + it * 256;
        float v = 0.f;
        if (sIdx < Nn && sIdx != d) {
            float x = elb[sIdx] + erd;
            x = x > 0.f ? x : 0.2f * x;    // leaky relu, slope 0.2
            v = expf(x);
        }
        vals[it] = v;
        s += v;
    }
    __shared__ float red[256];
    red[t] = s; __syncthreads();
    for (int o = 128; o > 0; o >>= 1) {
        if (t < o) red[t] += red[t + o];
        __syncthreads();
    }
    float inv = 1.f / red[0];
    #pragma unroll
    for (int it = 0; it < 3; it++) {
        int sIdx = t + it * 256;
        if (sIdx < Nn) pr[sIdx] = vals[it] * inv;
    }
}

// ---------------------------------------------------------------------------
// Column means of x over rows [rowOff, rowOff+cnt) of each batch sample.
// grid = (Bb, Pp/128), 128 threads.
// ---------------------------------------------------------------------------
__global__ void mean_kernel(const float* __restrict__ x, float* __restrict__ out,
                            int rowOff, int cnt)
{
    int b = blockIdx.x;
    int p = blockIdx.y * 128 + threadIdx.x;
    const float* base = x + ((long)b * Nn + rowOff) * Pp + p;
    float s = 0.f;
    for (int i = 0; i < cnt; i++) s += base[(long)i * Pp];
    out[b * Pp + p] = s / (float)cnt;
}

// ---------------------------------------------------------------------------
// Symmetric KL partial per batch row: part[b] = sum_c exp(lq)(lq-lp),
// part[Bb+b] = sum_c exp(lp)(lp-lq). Exact log-softmax in fp32.
// ---------------------------------------------------------------------------
__global__ void kl_kernel(const float* __restrict__ Pm, long sp,
                          const float* __restrict__ Qm, long sq,
                          int D, float* __restrict__ part)
{
    int b = blockIdx.x;
    const float* p = Pm + b * sp;
    const float* q = Qm + b * sq;
    int t = threadIdx.x;   // 128
    __shared__ float s1[128], s2[128];

    float mp = -1e30f, mq = -1e30f;
    for (int c = t; c < D; c += 128) { mp = fmaxf(mp, p[c]); mq = fmaxf(mq, q[c]); }
    s1[t] = mp; s2[t] = mq; __syncthreads();
    for (int o = 64; o > 0; o >>= 1) {
        if (t < o) { s1[t] = fmaxf(s1[t], s1[t + o]); s2[t] = fmaxf(s2[t], s2[t + o]); }
        __syncthreads();
    }
    float MP = s1[0], MQ = s2[0];
    __syncthreads();

    float ssp = 0.f, ssq = 0.f;
    for (int c = t; c < D; c += 128) { ssp += expf(p[c] - MP); ssq += expf(q[c] - MQ); }
    s1[t] = ssp; s2[t] = ssq; __syncthreads();
    for (int o = 64; o > 0; o >>= 1) {
        if (t < o) { s1[t] += s1[t + o]; s2[t] += s2[t + o]; }
        __syncthreads();
    }
    float lsep = MP + logf(s1[0]);
    float lseq = MQ + logf(s2[0]);
    __syncthreads();

    float kpq = 0.f, kqp = 0.f;
    for (int c = t; c < D; c += 128) {
        float lp = p[c] - lsep, lq = q[c] - lseq;
        kpq += expf(lq) * (lq - lp);
        kqp += expf(lp) * (lp - lq);
    }
    s1[t] = kpq; s2[t] = kqp; __syncthreads();
    for (int o = 64; o > 0; o >>= 1) {
        if (t < o) { s1[t] += s1[t + o]; s2[t] += s2[t + o]; }
        __syncthreads();
    }
    if (t == 0) { part[b] = s1[0]; part[Bb + b] = s2[0]; }
}

__global__ void kl_final(const float* __restrict__ part, float* __restrict__ out)
{
    int t = threadIdx.x;   // 32
    float a = part[t], b = part[Bb + t];
    for (int o = 16; o > 0; o >>= 1) {
        a += __shfl_down_sync(0xffffffff, a, o);
        b += __shfl_down_sync(0xffffffff, b, o);
    }
    if (t == 0) out[0] = 0.5f * (a + b);
}

// ---------------------------------------------------------------------------
// Host launch
// ---------------------------------------------------------------------------
static inline void launch_gemm(const float* A, const float* B, const float* bias,
                               float* C, int M, int N, int K, int ldc,
                               long sA, long sB, long sC, int batches,
                               int mode, int rowsPer, int rowOff)
{
    dim3 grid((N + BN - 1) / BN, (M + BM - 1) / BM, batches);
    sgemm_kernel<<<grid, 256>>>(A, B, bias, C, M, N, K, ldc, sA, sB, sC,
                                mode, rowsPer, rowOff);
}

extern "C" void kernel_launch(void* const* d_in, const int* in_sizes, int n_in,
                              void* d_out, int out_size)
{
    const float* utt_t = (const float*)d_in[0];
    const float* utt_v = (const float*)d_in[1];
    const float* Wpt   = (const float*)d_in[2];
    const float* bpt   = (const float*)d_in[3];
    const float* Wpv   = (const float*)d_in[4];
    const float* bpv   = (const float*)d_in[5];
    const float* Ws    = (const float*)d_in[6];
    const float* bs    = (const float*)d_in[7];
    const float* Wproj = (const float*)d_in[8];
    const float* bproj = (const float*)d_in[9];
    const float* Wg    = (const float*)d_in[10];
    const float* al    = (const float*)d_in[11];
    const float* ar    = (const float*)d_in[12];
    const float* Wc    = (const float*)d_in[13];
    const float* bc    = (const float*)d_in[14];
    float* out = (float*)d_out;

    float *ft, *fv, *x, *h, *gat, *Pm, *el, *er, *hgi, *hgt, *part;
    cudaGetSymbolAddress((void**)&ft,  g_feat_t);
    cudaGetSymbolAddress((void**)&fv,  g_feat_v);
    cudaGetSymbolAddress((void**)&x,   g_x);
    cudaGetSymbolAddress((void**)&h,   g_h);
    cudaGetSymbolAddress((void**)&gat, g_gat);
    cudaGetSymbolAddress((void**)&Pm,  g_Pmat);
    cudaGetSymbolAddress((void**)&el,  g_el);
    cudaGetSymbolAddress((void**)&er,  g_er);
    cudaGetSymbolAddress((void**)&hgi, g_hgi);
    cudaGetSymbolAddress((void**)&hgt, g_hgt);
    cudaGetSymbolAddress((void**)&part,g_part);

    const long EMB = (long)Bb * Nn * Cc;

    for (int branch = 0; branch < 2; branch++) {
        const float* Wt = (branch == 0) ? Wpt : Ws;
        const float* bt = (branch == 0) ? bpt : bs;
        const float* Wv = (branch == 0) ? Wpv : Ws;
        const float* bv = (branch == 0) ? bpv : bs;
        float* emb_out = out + (branch == 0 ? 0 : EMB);

        // sigmoid projections
        launch_gemm(utt_t, Wt, bt, ft, Bb * Tt, Hh, Hh, Hh, 0, 0, 0, 1, ACT_SIG, 0, 0);
        launch_gemm(utt_v, Wv, bv, fv, Bb * Ii, Hh, Hh, Hh, 0, 0, 0, 1, ACT_SIG, 0, 0);

        // relu projection into concatenated x: rows [0,I) = v, [I,N) = t
        launch_gemm(fv, Wproj, bproj, x, Bb * Ii, Pp, Hh, Pp, 0, 0, 0, 1, ACT_RELU, Ii, 0);
        launch_gemm(ft, Wproj, bproj, x, Bb * Tt, Pp, Hh, Pp, 0, 0, 0, 1, ACT_RELU, Tt, Ii);

        if (branch == 1) {
            // readout means for share_loss (before x is reused next branch — it isn't, but safe)
            mean_kernel<<<dim3(Bb, Pp / 128), 128>>>(x, hgi, 0, Ii);
            mean_kernel<<<dim3(Bb, Pp / 128), 128>>>(x, hgt, Ii, Tt);
        }

        // GAT: h = x @ Wg
        launch_gemm(x, Wg, nullptr, h, Bb * Nn, Gg, Pp, Gg, 0, 0, 0, 1, ACT_NONE, 0, 0);
        // el/er scores
        score_kernel<<<Bb * Nn, 128>>>(h, al, ar, el, er);
        // normalized softmax attention matrix (diag excluded)
        build_p_kernel<<<Bb * Nn, 256>>>(el, er, Pm);
        // batched: gat = elu(P @ h)
        launch_gemm(Pm, h, nullptr, gat, Nn, Gg, Nn, Gg,
                    (long)Nn * Nn, (long)Nn * Gg, (long)Nn * Gg, Bb, ACT_ELU, 0, 0);
        // emb = gat @ Wc + bc  -> directly into output
        launch_gemm(gat, Wc, bc, emb_out, Bb * Nn, Cc, Gg, Cc, 0, 0, 0, 1, ACT_NONE, 0, 0);
    }

    // share_loss = sym_kl(hg_i, hg_t) over [B, P]
    kl_kernel<<<Bb, 128>>>(hgi, (long)Pp, hgt, (long)Pp, Pp, part);
    kl_final<<<1, 32>>>(part, out + 2 * EMB);

    // graph_loss = sym_kl(share_emb[:,0,:], private_emb[:,0,:]) over [B, C]
    kl_kernel<<<Bb, 128>>>(out + EMB, (long)Nn * Cc, out, (long)Nn * Cc, Cc, part);
    kl_final<<<1, 32>>>(part, out + 2 * EMB + 1);
}